// round 16
// baseline (speedup 1.0000x reference)
#include <cuda_runtime.h>
#include <cstdint>

// Local2d as 1024 GEMMs C[o,b] = sum_k W[o,k]*P[b,k], M=128, N=64, K=576.
// tf32 mma.sync.m16n8k8. Round 16 = round 14 with the gather scatter-address
// fixed (XOR swizzle applied to the complete word, matching the MMA reader).
// Quad-row P gather: each 4-lane quad loads one contiguous 3-float x row
// window -> 8 distinct 128B lines per warp-LDG. W: 3-stage cp.async.

#define KTOT  576
#define KC    32
#define NCH   18
#define APAD  36
#define A_WORDS (128 * APAD)              // 4608
#define B_WORDS 2048
#define STAGE_WORDS (A_WORDS + B_WORDS)   // 6656
#define AOFF(s) ((s) * STAGE_WORDS)
#define BOFF(s) ((s) * STAGE_WORDS + A_WORDS)
#define SMEM_BYTES (3 * STAGE_WORDS * 4)  // 79872
#define W_STRIDE_O (1024 * KTOT)

__device__ float g_scratch[1024 * 128 * 64];   // [loc][o][b] (32MB, L2-resident)

__device__ __forceinline__ uint32_t f2tf32(float f) {
    uint32_t u;
    asm("cvt.rna.tf32.f32 %0, %1;" : "=r"(u) : "f"(f));
    return u;
}
__device__ __forceinline__ uint32_t smem_u32(const void* p) {
    uint32_t a;
    asm("{ .reg .u64 t; cvta.to.shared.u64 t, %1; cvt.u32.u64 %0, t; }" : "=r"(a) : "l"(p));
    return a;
}
__device__ __forceinline__ void cp16(uint32_t dst, const float* src) {
    asm volatile("cp.async.cg.shared.global [%0], [%1], 16;" :: "r"(dst), "l"(src));
}
#define CP_COMMIT() asm volatile("cp.async.commit_group;" ::: "memory")
#define CP_WAIT(n)  asm volatile("cp.async.wait_group %0;" :: "n"(n) : "memory")

__device__ __forceinline__ void mma_tf32(float* d, const uint32_t* a, uint32_t b0, uint32_t b1) {
    asm volatile(
        "mma.sync.aligned.m16n8k8.row.col.f32.tf32.tf32.f32 "
        "{%0,%1,%2,%3}, {%4,%5,%6,%7}, {%8,%9}, {%0,%1,%2,%3};"
        : "+f"(d[0]), "+f"(d[1]), "+f"(d[2]), "+f"(d[3])
        : "r"(a[0]), "r"(a[1]), "r"(a[2]), "r"(a[3]), "r"(b0), "r"(b1));
}

__global__ __launch_bounds__(128, 2)
void local2d_mma_kernel(const float* __restrict__ x,
                        const float* __restrict__ weight)
{
    extern __shared__ uint32_t sm[];
    const uint32_t sbase = smem_u32(sm);
    const int tid  = threadIdx.x;
    const int warp = tid >> 5;
    const int lane = tid & 31;
    const int g    = lane >> 2;
    const int t    = lane & 3;
    const int wo   = warp * 32;
    const int loc  = blockIdx.x;
    const int h    = loc >> 5, w = loc & 31;

    // W cp.async addressing: thread covers o = o0+16j, fixed k-quad q
    const int o0 = tid >> 3;
    const int q8 = tid & 7;
    const float* wsrc0 = weight + (size_t)loc * KTOT + (size_t)o0 * W_STRIDE_O + q8 * 4;
    const uint32_t adst0 = o0 * 144 + q8 * 16;
    // P quad-gather: quad qd owns two b rows, lane-in-quad l4 = dw (3 = idle)
    const int qd = tid >> 2;
    const int l4 = tid & 3;

    float d[2][8][4];
#pragma unroll
    for (int i = 0; i < 2; i++)
#pragma unroll
        for (int j = 0; j < 8; j++)
#pragma unroll
            for (int e = 0; e < 4; e++) d[i][j][e] = 0.f;

    auto issue_W = [&](int c, int stage) {
        const float* src = wsrc0 + c * KC;
        uint32_t dst = sbase + AOFF(stage) * 4 + adst0;
#pragma unroll
        for (int j = 0; j < 8; j++)
            cp16(dst + j * 2304, src + (size_t)j * 16 * W_STRIDE_O);
        CP_COMMIT();
    };

    // quad-row gather: (b, rr) -> 3 contiguous floats x[b][ci][hh][w-1..w+1]
    auto gather_P = [&](int c, int stage) {
        if (l4 >= 3) return;
        uint32_t* Bb = sm + BOFF(stage);
        const int k0  = c * KC;
        const int rr0 = k0 / 3;
        const int ww  = w - 1 + l4;
        const bool vw = ((unsigned)ww < 32u);
#pragma unroll
        for (int rj = 0; rj < 12; rj++) {
            int rr = rr0 + rj;
            int k  = rr * 3 + l4 - k0;           // k within chunk
            if (k < 0 || k >= 32) continue;
            int ci = rr / 3;
            int dh = rr - ci * 3;
            int hh = h - 1 + dh;
            bool vx = vw && ((unsigned)hh < 32u);
            int ks = k >> 3, klo = k & 7;
            int t2 = klo & 3, hf = klo >> 2;
#pragma unroll
            for (int half = 0; half < 2; half++) {
                int b  = half * 32 + qd;
                int nt = b >> 3, g2 = b & 7;
                // EXACT reader formula (XOR over the complete word)
                int word = (ks * 512 + nt * 64 + (g2 * 4 + t2) * 2 + hf) ^ (ks << 3);
                float v = vx ? __ldg(x + (((b << 6) + ci) << 10) + (hh << 5) + ww) : 0.f;
                Bb[word] = f2tf32(v);
            }
        }
    };

    // ---- prologue: stages 0,1 in flight ----
    issue_W(0, 0);
    issue_W(1, 1);
    gather_P(0, 0);
    gather_P(1, 1);

#pragma unroll 1
    for (int c = 0; c < NCH; c++) {
        if (c < NCH - 1) CP_WAIT(1); else CP_WAIT(0);
        __syncthreads();                          // stage c%3 (W+P) published

        if (c + 2 < NCH) {                        // refill stage (c+2)%3 (readers done)
            issue_W(c + 2, (c + 2) % 3);
            gather_P(c + 2, (c + 2) % 3);
        }

        const uint32_t* Ab = sm + AOFF(c % 3);
        const uint32_t* Bb = sm + BOFF(c % 3);
        const float*    Ar = (const float*)Ab + (wo + g) * APAD;

#pragma unroll
        for (int ks = 0; ks < 4; ks++) {
            uint32_t a[2][4];
#pragma unroll
            for (int mt = 0; mt < 2; mt++) {
                const float* ap = Ar + mt * (16 * APAD) + ks * 8 + t;
                a[mt][0] = f2tf32(ap[0]);
                a[mt][1] = f2tf32(ap[8 * APAD]);
                a[mt][2] = f2tf32(ap[4]);
                a[mt][3] = f2tf32(ap[8 * APAD + 4]);
            }
#pragma unroll
            for (int nt = 0; nt < 8; nt++) {
                int word = (ks * 512 + nt * 64 + lane * 2) ^ (ks << 3);
                uint2 bb = *(const uint2*)(Bb + word);
                mma_tf32(d[0][nt], a[0], bb.x, bb.y);
                mma_tf32(d[1][nt], a[1], bb.x, bb.y);
            }
        }
    }

    // ---- epilogue -> scratch[loc][o][b] ----
    float* sc = g_scratch + (size_t)loc * (128 * 64);
#pragma unroll
    for (int mt = 0; mt < 2; mt++)
#pragma unroll
        for (int ab = 0; ab < 2; ab++) {
            int r = wo + mt * 16 + ab * 8 + g;
#pragma unroll
            for (int nt = 0; nt < 8; nt++) {
                float2 v = make_float2(d[mt][nt][ab * 2 + 0], d[mt][nt][ab * 2 + 1]);
                *(float2*)(sc + r * 64 + nt * 8 + 2 * t) = v;
            }
        }
}

// ---- kernel 2: scratch[loc][o][b] -> out[b][o][loc] + bias ----
__global__ __launch_bounds__(256)
void transpose_bias_kernel(const float* __restrict__ bias,
                           float* __restrict__ out)
{
    __shared__ float s2[32][65];
    const int loc0 = blockIdx.x * 32;
    const int o    = blockIdx.y;
    const int tid  = threadIdx.x;

    {
        const int c = tid & 63, r0 = tid >> 6;
#pragma unroll
        for (int i = 0; i < 8; i++) {
            int r = i * 4 + r0;
            s2[r][c] = g_scratch[((size_t)(loc0 + r) * 128 + o) * 64 + c];
        }
    }
    __syncthreads();

    const int lc = tid & 31;
    const int b0 = tid >> 5;
    const float bv = bias[(o << 10) + loc0 + lc];
#pragma unroll
    for (int i = 0; i < 8; i++) {
        int b = i * 8 + b0;
        out[((size_t)(b * 128 + o) << 10) + loc0 + lc] = s2[lc][b] + bv;
    }
}

// parity shims: make launch period 5 so ncu (-s 5 -c 1) profiles kernel 1
__global__ void dummy_k() {}

extern "C" void kernel_launch(void* const* d_in, const int* in_sizes, int n_in,
                              void* d_out, int out_size) {
    const float* x      = (const float*)d_in[0];
    const float* weight = (const float*)d_in[1];
    const float* bias   = (const float*)d_in[2];
    float* out = (float*)d_out;

    cudaFuncSetAttribute(local2d_mma_kernel,
                         cudaFuncAttributeMaxDynamicSharedMemorySize, SMEM_BYTES);
    local2d_mma_kernel<<<1024, 128, SMEM_BYTES>>>(x, weight);
    transpose_bias_kernel<<<dim3(32, 128), 256>>>(bias, out);
    dummy_k<<<1, 32>>>();
    dummy_k<<<1, 32>>>();
    dummy_k<<<1, 32>>>();
}